// round 7
// baseline (speedup 1.0000x reference)
#include <cuda_runtime.h>
#include <math.h>

#define NB   128   // batch
#define NC   64    // channels
#define NH   64
#define NW   64
#define NPIX (NH*NW)
#define KK   49

typedef unsigned long long u64;

// ---- packed fp32x2 helpers (sm_100+ PTX; full IEEE fp32 per lane) ----------
__device__ __forceinline__ u64 splat2(float a) {
    u64 r; asm("mov.b64 %0, {%1,%1};" : "=l"(r) : "f"(a)); return r;
}
__device__ __forceinline__ void fma2(u64& d, u64 a, u64 b) {
    asm("fma.rn.f32x2 %0, %1, %2, %0;" : "+l"(d) : "l"(a), "l"(b));
}
__device__ __forceinline__ float2 upk(u64 v) {
    float2 f; asm("mov.b64 {%0,%1}, %2;" : "=f"(f.x), "=f"(f.y) : "l"(v)); return f;
}
#define GETC(v,cc) ((cc)==0?(v).x:(cc)==1?(v).y:(cc)==2?(v).z:(v).w)

// ---------------- scratch (device globals; no allocations allowed) ----------
// Layout: [b][cb=0..3][pix][16ch]  (cb = 16-channel block)
__device__ __align__(16) float g_rubinw[NB*NPIX*NC];
__device__ __align__(16) float g_visn  [NB*NPIX*NC];
__device__ float g_costpart[NB*8*KK];
__device__ float g_poolr[NB*NH*NC];
__device__ float g_poolv[NB*NH*NC];
__device__ float g_Spart[NB*NH];

// =========================== Kernel A =======================================
// One block per (b, 2-row pair). 256 threads, 8 warps, TENSOR-SPECIALIZED:
// warps 0-3 -> rubin, warps 4-7 -> vis. Each warp owns 16 outputs; each
// thread owns 4 pixels -> 32 u64 f32x2 accumulators.
#define OFF_WR  0
#define OFF_WV  4352
#define OFF_XR  8704
#define OFF_XV  17408
#define OFF_SQR 26112
#define OFF_SQV 26624
#define OFF_PR  27136
#define OFF_PV  27648
#define OFF_GX  28160
#define OFF_FR  28224
#define OFF_SV  28352
#define OFF_SW  28480
#define KA_SMEM_FLOATS 28608

__global__ void __launch_bounds__(256, 2)
kA(const float* __restrict__ rubin, const float* __restrict__ vis,
   const float* __restrict__ wr, const float* __restrict__ wv, float inv_gsum)
{
    extern __shared__ float sm[];
    float* sWr = sm + OFF_WR;    // [c][o], stride 68
    float* sWv = sm + OFF_WV;
    float* sXr = sm + OFF_XR;    // [pix][c], 128 pixels, stride 68
    float* sXv = sm + OFF_XV;
    float* sSQR = sm + OFF_SQR;  // [4][128]
    float* sSQV = sm + OFF_SQV;  // [4][128]
    float* sPr = sm + OFF_PR;    // [2rows][4q][64c]
    float* sPv = sm + OFF_PV;
    float* sGx = sm + OFF_GX;    // [64]
    float* sFr = sm + OFF_FR;    // [128]
    float* sSv = sm + OFF_SV;    // [128]
    float* sSw = sm + OFF_SW;    // [128]

    const int h0 = blockIdx.x * 2, b = blockIdx.y;
    const int tid = threadIdx.x;
    const int wid = tid >> 5, lane = tid & 31;
    const bool isR = (wid < 4);

    // ---- weights -> smem transposed [c][o] (coalesced global read) ----
    for (int idx = tid; idx < 4096; idx += 256) {
        int o = idx >> 6, c = idx & 63;
        sWr[c*68 + o] = wr[idx];
        sWv[c*68 + o] = wv[idx];
    }
    if (tid < 64) {
        float xxg = -1.f + 2.f * (float)tid / 63.f;
        sGx[tid] = expf(-2.f * xxg * xxg);
    }

    // ---- stage x transposed: sX[pix][c], pix = r*64 + w ----
    {
        const int w0 = tid & 63, cq = tid >> 6;
#pragma unroll
        for (int r = 0; r < 2; r++) {
            const size_t rowbase = (size_t)b*NC*NPIX + (size_t)(h0 + r)*64 + w0;
            const int pofs = (r*64 + w0)*68;
#pragma unroll
            for (int it = 0; it < 4; it++) {
                int c0 = cq*4 + it*16;
                float4 vr, vv;
                vr.x = rubin[rowbase + (size_t)(c0+0)*NPIX];
                vr.y = rubin[rowbase + (size_t)(c0+1)*NPIX];
                vr.z = rubin[rowbase + (size_t)(c0+2)*NPIX];
                vr.w = rubin[rowbase + (size_t)(c0+3)*NPIX];
                vv.x = vis  [rowbase + (size_t)(c0+0)*NPIX];
                vv.y = vis  [rowbase + (size_t)(c0+1)*NPIX];
                vv.z = vis  [rowbase + (size_t)(c0+2)*NPIX];
                vv.w = vis  [rowbase + (size_t)(c0+3)*NPIX];
                *(float4*)&sXr[pofs + c0] = vr;
                *(float4*)&sXv[pofs + c0] = vv;
            }
        }
    }
    __syncthreads();

    // ---- f32x2 register-tiled GEMM (one tensor per warp, 4 pixels/thread) --
    const int og = (wid & 3) * 16;
    const float* sX = isR ? sXr : sXv;
    const float* sW = isR ? sWr : sWv;

    u64 acc[4][8];     // [pixel][output-pair]
#pragma unroll
    for (int pp = 0; pp < 4; pp++)
#pragma unroll
        for (int j = 0; j < 8; j++) acc[pp][j] = 0ull;

#pragma unroll 2
    for (int c0 = 0; c0 < 64; c0 += 4) {
        float4 x[4];
#pragma unroll
        for (int pp = 0; pp < 4; pp++)
            x[pp] = *(const float4*)&sX[(lane + 32*pp)*68 + c0];
#pragma unroll
        for (int cc = 0; cc < 4; cc++) {
            const int c = c0 + cc;
            const ulonglong2 wa = *(const ulonglong2*)&sW[c*68 + og];
            const ulonglong2 wb = *(const ulonglong2*)&sW[c*68 + og + 4];
            const ulonglong2 wc = *(const ulonglong2*)&sW[c*68 + og + 8];
            const ulonglong2 wd = *(const ulonglong2*)&sW[c*68 + og + 12];
#pragma unroll
            for (int pp = 0; pp < 4; pp++) {
                const u64 s = splat2(GETC(x[pp], cc));
                fma2(acc[pp][0], wa.x, s); fma2(acc[pp][1], wa.y, s);
                fma2(acc[pp][2], wb.x, s); fma2(acc[pp][3], wb.y, s);
                fma2(acc[pp][4], wc.x, s); fma2(acc[pp][5], wc.y, s);
                fma2(acc[pp][6], wd.x, s); fma2(acc[pp][7], wd.y, s);
            }
        }
    }

    // ---- pool partials over raw x (still resident in sXr/sXv) ----
    {
        const int c = tid & 63, q = tid >> 6;
#pragma unroll
        for (int r = 0; r < 2; r++) {
            float pr = 0.f, pv = 0.f;
#pragma unroll
            for (int w = 0; w < 16; w++) {
                const int wcol = q*16 + w;
                const int px = r*64 + wcol;
                const float gxw = sGx[wcol];
                pr = fmaf(sXr[px*68 + c], gxw, pr);
                pv = fmaf(sXv[px*68 + c], gxw, pv);
            }
            sPr[(r*4 + q)*64 + c] = pr;
            sPv[(r*4 + q)*64 + c] = pv;
        }
    }

    // ---- per-(warp,pixel) square partials over this warp's 16 outputs ----
    {
        float* sSQ = isR ? sSQR : sSQV;
#pragma unroll
        for (int pp = 0; pp < 4; pp++) {
            float sq = 0.f;
#pragma unroll
            for (int j = 0; j < 8; j++) {
                float2 t = upk(acc[pp][j]);
                sq = fmaf(t.x, t.x, fmaf(t.y, t.y, sq));
            }
            sSQ[(wid & 3)*128 + lane + 32*pp] = sq;
        }
    }
    __syncthreads();

    if (tid < 128) {
        const int pix = tid;           // r*64 + col
        const int r = pix >> 6, col = pix & 63;
        float ssr = 0.f, ssv = 0.f;
#pragma unroll
        for (int w = 0; w < 4; w++) { ssr += sSQR[w*128 + pix]; ssv += sSQV[w*128 + pix]; }
        const float sr = 1.f / fmaxf(sqrtf(ssr), 1e-6f);
        const float sv = 1.f / fmaxf(sqrtf(ssv), 1e-6f);
        const float e  = ssr * sr * sr;
        const float yy = -1.f + 2.f * (float)(h0 + r) / 63.f;
        const float gy = expf(-2.f*yy*yy);
        const float g  = gy * sGx[col] * inv_gsum;
        const float swraw = e * g;
        sFr[pix] = sr * swraw;
        sSv[pix] = sv;
        sSw[pix] = swraw;
        const float gyn = gy * inv_gsum;
        const int c = col;
        g_poolr[(b*NH + h0 + r)*NC + c] =
            (sPr[(r*4+0)*64+c] + sPr[(r*4+1)*64+c] + sPr[(r*4+2)*64+c] + sPr[(r*4+3)*64+c]) * gyn;
        g_poolv[(b*NH + h0 + r)*NC + c] =
            (sPv[(r*4+0)*64+c] + sPv[(r*4+1)*64+c] + sPv[(r*4+2)*64+c] + sPv[(r*4+3)*64+c]) * gyn;
    }
    __syncthreads();

    if (tid < 2) {
        float s = 0.f;
        for (int i = 0; i < 64; i++) s += sSw[tid*64 + i];
        g_Spart[b*NH + h0 + tid] = s;
    }

    // ---- scale accums and re-stage into own tensor's sX (raw x now dead) ----
    {
        float* sXo = isR ? sXr : sXv;
#pragma unroll
        for (int pp = 0; pp < 4; pp++) {
            const int pix = lane + 32*pp;
            const float f = isR ? sFr[pix] : sSv[pix];
#pragma unroll
            for (int q = 0; q < 4; q++) {
                float2 ta = upk(acc[pp][2*q]), tb = upk(acc[pp][2*q+1]);
                float4 t; t.x = ta.x*f; t.y = ta.y*f; t.z = tb.x*f; t.w = tb.y*f;
                *(float4*)&sXo[pix*68 + og + 4*q] = t;
            }
        }
    }
    __syncthreads();

    // ---- coalesced global stores: layout [b][cb][pix][16] ----
    {
#pragma unroll
        for (int k = 0; k < 8; k++) {
            const int idx = k*256 + tid;      // f4 idx 0..2047
            const int q   = idx & 3;
            const int pix = (idx >> 2) & 127;
            const int cb  = idx >> 9;         // 0..3
            const size_t dst = ((size_t)(b*4 + cb)*NPIX + (size_t)h0*64 + pix)*16 + q*4;
            *(float4*)&g_rubinw[dst] = *(float4*)&sXr[pix*68 + cb*16 + q*4];
            *(float4*)&g_visn  [dst] = *(float4*)&sXv[pix*68 + cb*16 + q*4];
        }
    }
}

// =========================== Kernel B =======================================
// Correlation costs, channel-split threads. Block = (b, 8-row tile).
// 128 threads: q = tid&7 (channel PAIR within 16-ch chunk, one u64),
// cp = tid>>3 (4 columns: 4cp..4cp+3). Each thread covers ALL 8 rows.
// smem u64 layout: idx = t*640 + col*10 + q  -> word index mod 16 within a
// 16-lane phase is 8*cp + q: provably distinct -> conflict-free LDS.64.
#define KB_SMEM_BYTES (14*640*8)   // 71680

__global__ void __launch_bounds__(128, 2)
kB()
{
    const int tile = blockIdx.x;            // 0..7
    const int b    = blockIdx.y;
    const int h0   = tile * 8;
    const int tid  = threadIdx.x;
    const int q    = tid & 7;               // channel pair (2q, 2q+1)
    const int cp   = tid >> 3;              // 0..15, cols 4cp..4cp+3

    extern __shared__ u64 sv64[];           // [t*640 + col*10 + q]

    u64 acc2[KK];
#pragma unroll
    for (int k = 0; k < KK; k++) acc2[k] = 0ull;

    for (int cb = 0; cb < 4; cb++) {
        const float* vplane = g_visn   + (size_t)(b*4 + cb)*NPIX*16;
        const float* rplane = g_rubinw + (size_t)(b*4 + cb)*NPIX*16;

        __syncthreads();
        // stage 14 window rows x 64 cols x 16 ch, coalesced f4 reads,
        // f4 store = u64 pair at (col*10 + 2m) -> 16B aligned.
        for (int idx = tid; idx < 14*64*4; idx += 128) {
            const int m   = idx & 3;
            const int col = (idx >> 2) & 63;
            const int t   = idx >> 8;
            const int gr  = min(max(h0 + t - 3, 0), 63);
            *(float4*)&sv64[t*640 + col*10 + 2*m] =
                *(const float4*)(vplane + ((size_t)(gr*64 + col))*16 + m*4);
        }
        __syncthreads();

        // rubin registers: 8 rows x 4 cols x 2 ch (one u64 each)
        u64 rb[8][4];
#pragma unroll
        for (int r = 0; r < 8; r++)
#pragma unroll
            for (int cc = 0; cc < 4; cc++)
                rb[r][cc] = *(const u64*)(rplane +
                    ((size_t)((h0 + r)*64 + 4*cp + cc))*16 + q*2);

        // window loop: t = local window row (global h0 + t - 3)
#pragma unroll
        for (int t = 0; t < 14; t++) {
            u64 w[10];
#pragma unroll
            for (int j = 0; j < 10; j++) {
                const int colw = min(max(4*cp + j - 3, 0), 63);
                w[j] = sv64[t*640 + colw*10 + q];
            }
#pragma unroll
            for (int k = 0; k < 7; k++) {
                const int r = t - k;
                if (r >= 0 && r <= 7) {
#pragma unroll
                    for (int dx = 0; dx < 7; dx++) {
                        fma2(acc2[k*7 + dx], rb[r][0], w[dx]);
                        fma2(acc2[k*7 + dx], rb[r][1], w[dx+1]);
                        fma2(acc2[k*7 + dx], rb[r][2], w[dx+2]);
                        fma2(acc2[k*7 + dx], rb[r][3], w[dx+3]);
                    }
                }
            }
        }
    }

    __shared__ float sred[4][KK];
    const int wid = tid >> 5, lane = tid & 31;
#pragma unroll
    for (int k = 0; k < KK; k++) {
        float2 t = upk(acc2[k]);
        float v = t.x + t.y;
#pragma unroll
        for (int off = 16; off > 0; off >>= 1) v += __shfl_down_sync(0xffffffffu, v, off);
        if (lane == 0) sred[wid][k] = v;
    }
    __syncthreads();
    if (tid < KK)
        g_costpart[(b*8 + tile)*KK + tid] =
            sred[0][tid] + sred[1][tid] + sred[2][tid] + sred[3][tid];
}

// =========================== Kernel C =======================================
__device__ __forceinline__ float gelu_exact(float x) {
    return 0.5f * x * (1.f + erff(x * 0.70710678118654752440f));
}

__global__ void __launch_bounds__(128)
kC(const float* __restrict__ p2s, const int* __restrict__ band_idx,
   const float* __restrict__ log_temp, const float* __restrict__ band_emb,
   const float* __restrict__ w1, const float* __restrict__ b1,
   const float* __restrict__ w2, const float* __restrict__ b2,
   const float* __restrict__ w3, const float* __restrict__ b3,
   float* __restrict__ out, int stride)
{
    const int b = blockIdx.x, tid = threadIdx.x;
    __shared__ float sfeat[212];
    __shared__ float scost[KK];
    __shared__ float sh1[128], sh2[128], sout3[3];
    __shared__ float sS, scdx, scdy, sconf;

    if (tid == 0) {
        float s = 0.f;
        for (int h = 0; h < NH; h++) s += g_Spart[b*NH + h];
        sS = s;
    }
    if (tid < KK) {
        float c = 0.f;
        for (int t = 0; t < 8; t++) c += g_costpart[(b*8 + t)*KK + tid];
        scost[tid] = c;
    }
    if (tid < 64) {
        float pr = 0.f, pv = 0.f;
        for (int h = 0; h < NH; h++) {
            pr += g_poolr[(b*NH + h)*NC + tid];
            pv += g_poolv[(b*NH + h)*NC + tid];
        }
        sfeat[tid] = pr; sfeat[64 + tid] = pv; sfeat[128 + tid] = pr - pv;
    }
    __syncthreads();

    if (tid == 0) {
        const float temp  = fmaxf(expf(log_temp[0]), 1e-3f);
        const float scale = 1.f / ((sS + 1e-8f) * 8.f * temp);  // sqrt(C)=8
        float l[KK], mx = -1e30f;
        for (int k = 0; k < KK; k++) { l[k] = scost[k] * scale; mx = fmaxf(mx, l[k]); }
        float sum = 0.f;
        for (int k = 0; k < KK; k++) { float p = expf(l[k] - mx); l[k] = p; sum += p; }
        const float inv = 1.f / sum;
        float cdx = 0.f, cdy = 0.f, cf = 0.f;
        for (int k = 0; k < KK; k++) {
            float p = l[k] * inv;
            cf  = fmaxf(cf, p);
            cdx += p * (float)((k % 7) - 3);
            cdy += p * (float)((k / 7) - 3);
        }
        scdx = cdx; scdy = cdy; sconf = cf;
        sfeat[192] = cdx; sfeat[193] = cdy;
    }
    if (tid < 16) sfeat[194 + tid] = band_emb[band_idx[b]*16 + tid];
    __syncthreads();

    float a = b1[tid];
    for (int f = 0; f < 210; f++) a = fmaf(sfeat[f], w1[f*128 + tid], a);
    sh1[tid] = gelu_exact(a);
    __syncthreads();

    a = b2[tid];
    for (int f = 0; f < 128; f++) a = fmaf(sh1[f], w2[f*128 + tid], a);
    sh2[tid] = gelu_exact(a);
    __syncthreads();

    if (tid < 3) {
        float a3 = b3[tid];
        for (int f = 0; f < 128; f++) a3 = fmaf(sh2[f], w3[f*3 + tid], a3);
        sout3[tid] = a3;
    }
    __syncthreads();

    if (tid == 0) {
        const float dx = scdx + sout3[0];
        const float dy = scdy + sout3[1];
        const float ls = fminf(fmaxf(sout3[2], -6.f), 3.f);
        const float s0 = p2s[b*4 + 0]*dx + p2s[b*4 + 1]*dy;
        const float s1 = p2s[b*4 + 2]*dx + p2s[b*4 + 3]*dy;
        float* o = out + (size_t)b * stride;
        if (stride > 0) o[0] = dx;
        if (stride > 1) o[1] = dy;
        if (stride > 2) o[2] = s0;
        if (stride > 3) o[3] = s1;
        if (stride > 4) o[4] = ls;
        if (stride > 5) o[5] = sconf;
        for (int j = 6; j < stride; j++) o[j] = 0.f;
    }
}

// =========================== launch =========================================
extern "C" void kernel_launch(void* const* d_in, const int* in_sizes, int n_in,
                              void* d_out, int out_size)
{
    const float* rubin = (const float*)d_in[0];
    const float* vis   = (const float*)d_in[1];
    const float* p2s   = (const float*)d_in[2];
    const int*   bidx  = (const int*)  d_in[3];
    const float* wr    = (const float*)d_in[4];
    const float* wv    = (const float*)d_in[5];
    const float* lt    = (const float*)d_in[6];
    const float* bemb  = (const float*)d_in[7];
    const float* w1    = (const float*)d_in[8];
    const float* b1    = (const float*)d_in[9];
    const float* w2    = (const float*)d_in[10];
    const float* b2    = (const float*)d_in[11];
    const float* w3    = (const float*)d_in[12];
    const float* b3    = (const float*)d_in[13];
    float* out = (float*)d_out;
    const int stride = out_size / NB;

    // gauss normalizer (separable, H=W=64)
    double Sy = 0.0;
    for (int i = 0; i < 64; i++) {
        double y = -1.0 + 2.0 * (double)i / 63.0;
        Sy += exp(-2.0 * y * y);
    }
    const float inv_gsum = (float)(1.0 / (Sy * Sy));

    const int ka_smem = KA_SMEM_FLOATS * 4;   // 114432 B
    cudaFuncSetAttribute(kA, cudaFuncAttributeMaxDynamicSharedMemorySize, ka_smem);
    cudaFuncSetAttribute(kB, cudaFuncAttributeMaxDynamicSharedMemorySize, KB_SMEM_BYTES);

    kA<<<dim3(NH/2, NB), 256, ka_smem>>>(rubin, vis, wr, wv, inv_gsum);
    kB<<<dim3(8, NB), 128, KB_SMEM_BYTES>>>();
    kC<<<NB, 128>>>(p2s, bidx, lt, bemb, w1, b1, w2, b2, w3, b3, out, stride);
}